// round 12
// baseline (speedup 1.0000x reference)
#include <cuda_runtime.h>
#include <math_constants.h>

// Fixed shapes
#define B      32
#define C0     512
#define C1     1024
#define HW0    1444      // 38*38, divisible by 4
#define HW4_0  361       // HW0/4 in float4 units
#define HW1    361       // 19*19
#define THRESH 0.15f
#define NCH0   8         // channel chunks, level 0 (CPC = 64)
#define NCH1   16        // channel chunks, level 1 (CPC = 64)
#define CPC0   (C0/NCH0) // 64
#define CPC1   (C1/NCH1) // 64

// Output layout (float32): fw[2], embT0, embT1, embS0, embS1
#define OFF_FW  0
#define OFF_ET0 2
#define OFF_ET1 (OFF_ET0 + B*HW0)
#define OFF_ES0 (OFF_ET1 + B*HW1)
#define OFF_ES1 (OFF_ES0 + B*HW0)

// Static device scratch
__device__ float d_w0[B * C0];
__device__ float d_w1[B * C1];
__device__ float d_pc0[NCH0 * B * HW0];
__device__ float d_pt0[NCH0 * B * HW0];
__device__ float d_ps0[NCH0 * B * HW0];
__device__ float d_pc1[NCH1 * B * HW1];
__device__ float d_pt1[NCH1 * B * HW1];
__device__ float d_ps1[NCH1 * B * HW1];
__device__ float d_score[2 * B];
__device__ int   d_cnt = 0;
__device__ int   d_cnt0[B * NCH0];   // 256 w-chunk arrival counters, level 0
__device__ int   d_cnt1[B * NCH1];   // 512 w-chunk arrival counters, level 1

// ---------------------------------------------------------------------------
// Fused main kernel: 8704 blocks x 128 threads.
//  bids [0,6400): period-25 interleave (16 gmean + 9 Sf)  — R11 phase A
//  bids [6400,8704): Tf pass; spin-waits on its w-chunk counter
// ---------------------------------------------------------------------------
__global__ __launch_bounds__(128)
void k_main(const float* __restrict__ g0, const float* __restrict__ g1,
            const float* __restrict__ Sf0, const float* __restrict__ Sf1,
            const float* __restrict__ Tf0, const float* __restrict__ Tf1,
            float* __restrict__ w0, float* __restrict__ w1,
            float* __restrict__ pc0, float* __restrict__ pt0, float* __restrict__ ps0,
            float* __restrict__ pc1, float* __restrict__ pt1, float* __restrict__ ps1) {
    const int bid = blockIdx.x;
    const int tid = threadIdx.x;

    if (bid < 6400) {
        const int grp = bid / 25;
        const int r   = bid % 25;

        if (r < 16) {
            // ============ gmean segment (4096 virtual blocks) ============
            const int gblk = grp * 16 + r;          // 0..4095
            const int lane = tid & 31;
            const int warp = tid >> 5;              // 0..3

            if (gblk < 2048) {
                // level 0: one warp = 2 rows, float4. Block covers rows
                // [gblk*8, gblk*8+8) -> one w-chunk gets 8 such blocks.
                const int pair = gblk * 4 + warp;
                const float4* p0 = reinterpret_cast<const float4*>(g0) + (size_t)(2 * pair) * HW4_0;
                const float4* p1 = p0 + HW4_0;
                float4 a0 = {0,0,0,0}, a1 = {0,0,0,0};
                #pragma unroll 2
                for (int i = lane; i < HW4_0; i += 32) {
                    float4 v0 = __ldcs(p0 + i);
                    float4 v1 = __ldcs(p1 + i);
                    a0.x += v0.x; a0.y += v0.y; a0.z += v0.z; a0.w += v0.w;
                    a1.x += v1.x; a1.y += v1.y; a1.z += v1.z; a1.w += v1.w;
                }
                float s0 = (a0.x + a0.y) + (a0.z + a0.w);
                float s1 = (a1.x + a1.y) + (a1.z + a1.w);
                #pragma unroll
                for (int o = 16; o; o >>= 1) {
                    s0 += __shfl_xor_sync(0xffffffffu, s0, o);
                    s1 += __shfl_xor_sync(0xffffffffu, s1, o);
                }
                if (lane == 0) {
                    w0[2 * pair]     = s0 * (1.f / HW0);
                    w0[2 * pair + 1] = s1 * (1.f / HW0);
                    __threadfence();           // publish this warp's w stores
                }
                __syncthreads();
                if (tid == 0) atomicAdd(&d_cnt0[gblk >> 3], 1);   // release
            } else {
                // level 1: one warp = 4 rows, scalar interleaved. Block covers
                // rows [lblk*16, lblk*16+16) -> one w-chunk gets 4 blocks.
                const int lblk = gblk - 2048;        // 0..2047
                const int quad = lblk * 4 + warp;
                const float* p = g1 + (size_t)(4 * quad) * HW1;
                float s0 = 0.f, s1 = 0.f, s2 = 0.f, s3 = 0.f;
                #pragma unroll 2
                for (int i = lane; i < HW1; i += 32) {
                    s0 += __ldcs(p + i);
                    s1 += __ldcs(p + HW1 + i);
                    s2 += __ldcs(p + 2 * HW1 + i);
                    s3 += __ldcs(p + 3 * HW1 + i);
                }
                #pragma unroll
                for (int o = 16; o; o >>= 1) {
                    s0 += __shfl_xor_sync(0xffffffffu, s0, o);
                    s1 += __shfl_xor_sync(0xffffffffu, s1, o);
                    s2 += __shfl_xor_sync(0xffffffffu, s2, o);
                    s3 += __shfl_xor_sync(0xffffffffu, s3, o);
                }
                if (lane == 0) {
                    const float inv = 1.f / HW1;
                    w1[4 * quad]     = s0 * inv;
                    w1[4 * quad + 1] = s1 * inv;
                    w1[4 * quad + 2] = s2 * inv;
                    w1[4 * quad + 3] = s3 * inv;
                    __threadfence();
                }
                __syncthreads();
                if (tid == 0) atomicAdd(&d_cnt1[lblk >> 2], 1);
            }
        } else {
            // ============ Sf channel-sum segment (2304 virtual blocks) ============
            const int sblk = grp * 9 + (r - 16);    // 0..2303
            if (sblk < 768) {
                const int x = sblk % 3, b = (sblk / 3) % 32, chunk = sblk / 96;
                const int q = x * 128 + tid;
                if (q >= HW4_0) return;
                const float4* sp = reinterpret_cast<const float4*>(Sf0)
                                 + (size_t)(b * C0 + chunk * CPC0) * HW4_0 + q;
                float4 acc = {0,0,0,0};
                #pragma unroll 8
                for (int c = 0; c < CPC0; ++c) {
                    float4 s = __ldcs(sp + (size_t)c * HW4_0);
                    acc.x += s.x; acc.y += s.y; acc.z += s.z; acc.w += s.w;
                }
                reinterpret_cast<float4*>(ps0)[(size_t)(chunk * B + b) * HW4_0 + q] = acc;
            } else {
                const int t = sblk - 768;           // 0..1535
                const int x = t % 3, b = (t / 3) % 32, chunk = t / 96;
                const int hw = x * 128 + tid;
                if (hw >= HW1) return;
                const float* sp = Sf1 + (size_t)(b * C1 + chunk * CPC1) * HW1 + hw;
                float acc = 0.f;
                #pragma unroll 8
                for (int c = 0; c < CPC1; ++c) acc += __ldcs(sp + (size_t)c * HW1);
                ps1[(size_t)(chunk * B + b) * HW1 + hw] = acc;
            }
        }
    } else {
        // ============ Tf segment (2304 blocks), spin-wait on w chunk ============
        __shared__ float sw[64];
        const int t = bid - 6400;                   // 0..2303

        if (t < 768) {
            const int x = t % 3, b = (t / 3) % 32, chunk = t / 96;
            if (tid == 0) {
                const int* cp = &d_cnt0[b * NCH0 + chunk];
                while (__ldcg(cp) < 8) __nanosleep(64);
                __threadfence();                    // acquire
            }
            __syncthreads();
            if (tid < CPC0) sw[tid] = w0[b * C0 + chunk * CPC0 + tid];
            __syncthreads();

            const int q = x * 128 + tid;
            if (q >= HW4_0) return;
            const float4* tp = reinterpret_cast<const float4*>(Tf0)
                             + (size_t)(b * C0 + chunk * CPC0) * HW4_0 + q;
            float4 ac = {0,0,0,0}, at = {0,0,0,0};
            #pragma unroll 8
            for (int c = 0; c < CPC0; ++c) {
                float4 v = __ldcs(tp + (size_t)c * HW4_0);
                const float wv = sw[c];
                ac.x = fmaf(wv, v.x, ac.x); ac.y = fmaf(wv, v.y, ac.y);
                ac.z = fmaf(wv, v.z, ac.z); ac.w = fmaf(wv, v.w, ac.w);
                at.x += v.x; at.y += v.y; at.z += v.z; at.w += v.w;
            }
            const size_t o = (size_t)(chunk * B + b) * HW4_0 + q;
            reinterpret_cast<float4*>(pc0)[o] = ac;
            reinterpret_cast<float4*>(pt0)[o] = at;
        } else {
            const int u = t - 768;                  // 0..1535
            const int x = u % 3, b = (u / 3) % 32, chunk = u / 96;
            if (tid == 0) {
                const int* cp = &d_cnt1[b * NCH1 + chunk];
                while (__ldcg(cp) < 4) __nanosleep(64);
                __threadfence();
            }
            __syncthreads();
            if (tid < CPC1) sw[tid] = w1[b * C1 + chunk * CPC1 + tid];
            __syncthreads();

            const int hw = x * 128 + tid;
            if (hw >= HW1) return;
            const float* tp = Tf1 + (size_t)(b * C1 + chunk * CPC1) * HW1 + hw;
            float ac = 0.f, at = 0.f;
            #pragma unroll 8
            for (int c = 0; c < CPC1; ++c) {
                float v = __ldcs(tp + (size_t)c * HW1);
                ac = fmaf(sw[c], v, ac);
                at += v;
            }
            const size_t o = (size_t)(chunk * B + b) * HW1 + hw;
            pc1[o] = ac; pt1[o] = at;
        }
    }
}

// ---------------------------------------------------------------------------
// Finish: combine chunks + stats + mask + fw. 64 blocks x 1024 threads.
// Also resets the w-chunk counters for the next graph replay.
// ---------------------------------------------------------------------------
template <int C, int HW, int CHUNKS, int PPT>
__device__ __forceinline__
void finish_impl(const float* __restrict__ pc, const float* __restrict__ pt,
                 const float* __restrict__ ps,
                 float* __restrict__ outT, float* __restrict__ outS,
                 float* __restrict__ score_slot, int b,
                 float* smx, float* ssm, float* sthr) {
    constexpr float invC  = 1.f / (float)C;
    constexpr float invHW = 1.f / (float)HW;
    const int t = threadIdx.x;

    float camv[PPT], tv[PPT], sv[PPT];
    float mx = -CUDART_INF_F, sm = 0.f;

    #pragma unroll
    for (int p = 0; p < PPT; ++p) {
        const int i = p * 1024 + t;
        camv[p] = 0.f; tv[p] = 0.f; sv[p] = 0.f;
        if (i < HW) {
            float cc = 0.f, tt = 0.f, ss = 0.f;
            #pragma unroll
            for (int ch = 0; ch < CHUNKS; ++ch) {
                const size_t o = (size_t)(ch * B + b) * HW + i;
                cc += pc[o]; tt += pt[o]; ss += ps[o];
            }
            camv[p] = cc;
            tv[p]   = tt * invC;
            sv[p]   = ss * invC;
            mx = fmaxf(mx, cc);
            sm += fmaxf(cc, 0.f);
        }
    }

    smx[t] = mx; ssm[t] = sm;
    __syncthreads();
    #pragma unroll
    for (int s = 512; s; s >>= 1) {
        if (t < s) { smx[t] = fmaxf(smx[t], smx[t + s]); ssm[t] += ssm[t + s]; }
        __syncthreads();
    }
    if (t == 0) {
        *score_slot = ssm[0] * invHW;
        *sthr = fabsf(smx[0] * THRESH);
    }
    __syncthreads();
    const float thr = *sthr;

    #pragma unroll
    for (int p = 0; p < PPT; ++p) {
        const int i = p * 1024 + t;
        if (i < HW) {
            const bool m = camv[p] > thr;
            const size_t o = (size_t)b * HW + i;
            outT[o] = m ? tv[p] : 0.f;
            outS[o] = m ? sv[p] : 0.f;
        }
    }
}

__global__ __launch_bounds__(1024)
void k_finish_all(const float* __restrict__ pc0, const float* __restrict__ pt0,
                  const float* __restrict__ ps0,
                  const float* __restrict__ pc1, const float* __restrict__ pt1,
                  const float* __restrict__ ps1,
                  float* __restrict__ out, float* __restrict__ score) {
    __shared__ float smx[1024], ssm[1024];
    __shared__ float sthr;

    // Reset w-chunk counters for next replay (monster kernel already done).
    if (blockIdx.x == 0) {
        for (int i = threadIdx.x; i < B * NCH0; i += 1024) d_cnt0[i] = 0;
        for (int i = threadIdx.x; i < B * NCH1; i += 1024) d_cnt1[i] = 0;
    }

    if (blockIdx.x < 32) {
        const int b = blockIdx.x;
        finish_impl<C0, HW0, NCH0, 2>(pc0, pt0, ps0,
                                      out + OFF_ET0, out + OFF_ES0,
                                      score + b, b, smx, ssm, &sthr);
    } else {
        const int b = blockIdx.x - 32;
        finish_impl<C1, HW1, NCH1, 1>(pc1, pt1, ps1,
                                      out + OFF_ET1, out + OFF_ES1,
                                      score + B + b, b, smx, ssm, &sthr);
    }

    if (threadIdx.x == 0) {
        __threadfence();
        const int old = atomicAdd(&d_cnt, 1);
        if (old == 63) {
            __threadfence();
            float s0 = 0.f, s1 = 0.f;
            for (int i = 0; i < B; ++i) { s0 += score[i]; s1 += score[B + i]; }
            const float inv = 1.f / (s0 + s1);
            out[OFF_FW + 0] = s0 * inv;
            out[OFF_FW + 1] = s1 * inv;
            d_cnt = 0;   // reset for graph replay determinism
        }
    }
}

// ---------------------------------------------------------------------------
extern "C" void kernel_launch(void* const* d_in, const int* in_sizes, int n_in,
                              void* d_out, int out_size) {
    const float* Tf0 = (const float*)d_in[0];
    const float* Tf1 = (const float*)d_in[1];
    const float* Sf0 = (const float*)d_in[2];
    const float* Sf1 = (const float*)d_in[3];
    const float* g0  = (const float*)d_in[4];
    const float* g1  = (const float*)d_in[5];
    float* out = (float*)d_out;

    float *w0, *w1, *pc0, *pt0, *ps0, *pc1, *pt1, *ps1, *score;
    cudaGetSymbolAddress((void**)&w0,  d_w0);
    cudaGetSymbolAddress((void**)&w1,  d_w1);
    cudaGetSymbolAddress((void**)&pc0, d_pc0);
    cudaGetSymbolAddress((void**)&pt0, d_pt0);
    cudaGetSymbolAddress((void**)&ps0, d_ps0);
    cudaGetSymbolAddress((void**)&pc1, d_pc1);
    cudaGetSymbolAddress((void**)&pt1, d_pt1);
    cudaGetSymbolAddress((void**)&ps1, d_ps1);
    cudaGetSymbolAddress((void**)&score, d_score);

    // Fused phase A+B: gmean + Sf (interleaved) followed by spin-waiting Tf
    k_main<<<8704, 128>>>(g0, g1, Sf0, Sf1, Tf0, Tf1,
                          w0, w1, pc0, pt0, ps0, pc1, pt1, ps1);

    // Finish: combine + stats + mask + fw (+ counter reset)
    k_finish_all<<<64, 1024>>>(pc0, pt0, ps0, pc1, pt1, ps1, out, score);
}

// round 13
// speedup vs baseline: 1.0769x; 1.0769x over previous
#include <cuda_runtime.h>
#include <math_constants.h>

// Fixed shapes
#define B      32
#define C0     512
#define C1     1024
#define HW0    1444      // 38*38, divisible by 4
#define HW4_0  361       // HW0/4 in float4 units
#define HW1    361       // 19*19
#define THRESH 0.15f
#define NCH0   8         // channel chunks, level 0 (CPC = 64)
#define NCH1   16        // channel chunks, level 1 (CPC = 64)
#define CPC0   (C0/NCH0) // 64
#define CPC1   (C1/NCH1) // 64

// Output layout (float32): fw[2], embT0, embT1, embS0, embS1
#define OFF_FW  0
#define OFF_ET0 2
#define OFF_ET1 (OFF_ET0 + B*HW0)
#define OFF_ES0 (OFF_ET1 + B*HW1)
#define OFF_ES1 (OFF_ES0 + B*HW0)

// Static device scratch
__device__ float  d_w0[B * C0];
__device__ float  d_w1[B * C1];
__device__ float  d_pc0[NCH0 * B * HW0];
__device__ float  d_pt0[NCH0 * B * HW0];
__device__ float  d_ps0[NCH0 * B * HW0];
__device__ float  d_pc1[NCH1 * B * HW1];
__device__ float  d_pt1[NCH1 * B * HW1];
__device__ float  d_ps1[NCH1 * B * HW1];
__device__ float4 d_cam0[B * HW4_0];   // combined cam, level 0 (f4-aligned)
__device__ float  d_cam1[B * HW1];     // combined cam, level 1
__device__ float  d_pmax[2 * B];
__device__ float  d_psum[2 * B];
__device__ float  d_thr[2 * B];
__device__ int    d_cnt = 0;

// ---------------------------------------------------------------------------
// Phase A (R11 proven): gmean (g0+g1) AND Sf channel-sum partials, block
// indices interleaved period-25 (16 gmean + 9 Sf). 6400 blocks x 128.
// ---------------------------------------------------------------------------
__global__ __launch_bounds__(128)
void k_phaseA(const float* __restrict__ g0, const float* __restrict__ g1,
              const float* __restrict__ Sf0, const float* __restrict__ Sf1,
              float* __restrict__ w0, float* __restrict__ w1,
              float* __restrict__ ps0, float* __restrict__ ps1) {
    const int grp = blockIdx.x / 25;
    const int r   = blockIdx.x % 25;

    if (r < 16) {
        const int gblk = grp * 16 + r;          // 0..4095
        const int lane = threadIdx.x & 31;
        const int warp = threadIdx.x >> 5;

        if (gblk < 2048) {
            const int pair = gblk * 4 + warp;
            const float4* p0 = reinterpret_cast<const float4*>(g0) + (size_t)(2 * pair) * HW4_0;
            const float4* p1 = p0 + HW4_0;
            float4 a0 = {0,0,0,0}, a1 = {0,0,0,0};
            #pragma unroll 2
            for (int i = lane; i < HW4_0; i += 32) {
                float4 v0 = __ldcs(p0 + i);
                float4 v1 = __ldcs(p1 + i);
                a0.x += v0.x; a0.y += v0.y; a0.z += v0.z; a0.w += v0.w;
                a1.x += v1.x; a1.y += v1.y; a1.z += v1.z; a1.w += v1.w;
            }
            float s0 = (a0.x + a0.y) + (a0.z + a0.w);
            float s1 = (a1.x + a1.y) + (a1.z + a1.w);
            #pragma unroll
            for (int o = 16; o; o >>= 1) {
                s0 += __shfl_xor_sync(0xffffffffu, s0, o);
                s1 += __shfl_xor_sync(0xffffffffu, s1, o);
            }
            if (lane == 0) {
                w0[2 * pair]     = s0 * (1.f / HW0);
                w0[2 * pair + 1] = s1 * (1.f / HW0);
            }
        } else {
            const int quad = (gblk - 2048) * 4 + warp;
            const float* p = g1 + (size_t)(4 * quad) * HW1;
            float s0 = 0.f, s1 = 0.f, s2 = 0.f, s3 = 0.f;
            #pragma unroll 2
            for (int i = lane; i < HW1; i += 32) {
                s0 += __ldcs(p + i);
                s1 += __ldcs(p + HW1 + i);
                s2 += __ldcs(p + 2 * HW1 + i);
                s3 += __ldcs(p + 3 * HW1 + i);
            }
            #pragma unroll
            for (int o = 16; o; o >>= 1) {
                s0 += __shfl_xor_sync(0xffffffffu, s0, o);
                s1 += __shfl_xor_sync(0xffffffffu, s1, o);
                s2 += __shfl_xor_sync(0xffffffffu, s2, o);
                s3 += __shfl_xor_sync(0xffffffffu, s3, o);
            }
            if (lane == 0) {
                const float inv = 1.f / HW1;
                w1[4 * quad]     = s0 * inv;
                w1[4 * quad + 1] = s1 * inv;
                w1[4 * quad + 2] = s2 * inv;
                w1[4 * quad + 3] = s3 * inv;
            }
        }
    } else {
        const int sblk = grp * 9 + (r - 16);    // 0..2303
        const int tid  = threadIdx.x;

        if (sblk < 768) {
            const int x = sblk % 3, b = (sblk / 3) % 32, chunk = sblk / 96;
            const int q = x * 128 + tid;
            if (q >= HW4_0) return;
            const float4* sp = reinterpret_cast<const float4*>(Sf0)
                             + (size_t)(b * C0 + chunk * CPC0) * HW4_0 + q;
            float4 acc = {0,0,0,0};
            #pragma unroll 8
            for (int c = 0; c < CPC0; ++c) {
                float4 s = __ldcs(sp + (size_t)c * HW4_0);
                acc.x += s.x; acc.y += s.y; acc.z += s.z; acc.w += s.w;
            }
            reinterpret_cast<float4*>(ps0)[(size_t)(chunk * B + b) * HW4_0 + q] = acc;
        } else {
            const int t = sblk - 768;           // 0..1535
            const int x = t % 3, b = (t / 3) % 32, chunk = t / 96;
            const int hw = x * 128 + tid;
            if (hw >= HW1) return;
            const float* sp = Sf1 + (size_t)(b * C1 + chunk * CPC1) * HW1 + hw;
            float acc = 0.f;
            #pragma unroll 8
            for (int c = 0; c < CPC1; ++c) acc += __ldcs(sp + (size_t)c * HW1);
            ps1[(size_t)(chunk * B + b) * HW1 + hw] = acc;
        }
    }
}

// ---------------------------------------------------------------------------
// Phase B (R11 proven): Tf-only pass -> pc (weighted) and pt (plain sums).
// grid (3, B, NCH0+NCH1) = 2304 blocks x 128.
// ---------------------------------------------------------------------------
__global__ __launch_bounds__(128)
void k_camT(const float* __restrict__ Tf0, const float* __restrict__ w0,
            float* __restrict__ pc0, float* __restrict__ pt0,
            const float* __restrict__ Tf1, const float* __restrict__ w1,
            float* __restrict__ pc1, float* __restrict__ pt1) {
    __shared__ float sw[64];
    const int b = blockIdx.y, z = blockIdx.z, tid = threadIdx.x;

    if (z < NCH0) {
        const int chunk = z;
        if (tid < CPC0) sw[tid] = w0[b * C0 + chunk * CPC0 + tid];
        __syncthreads();

        const int q = blockIdx.x * 128 + tid;
        if (q >= HW4_0) return;
        const float4* tp = reinterpret_cast<const float4*>(Tf0)
                         + (size_t)(b * C0 + chunk * CPC0) * HW4_0 + q;
        float4 ac = {0,0,0,0}, at = {0,0,0,0};
        #pragma unroll 8
        for (int c = 0; c < CPC0; ++c) {
            float4 t = __ldcs(tp + (size_t)c * HW4_0);
            const float wv = sw[c];
            ac.x = fmaf(wv, t.x, ac.x); ac.y = fmaf(wv, t.y, ac.y);
            ac.z = fmaf(wv, t.z, ac.z); ac.w = fmaf(wv, t.w, ac.w);
            at.x += t.x; at.y += t.y; at.z += t.z; at.w += t.w;
        }
        const size_t o = (size_t)(chunk * B + b) * HW4_0 + q;
        reinterpret_cast<float4*>(pc0)[o] = ac;
        reinterpret_cast<float4*>(pt0)[o] = at;
    } else {
        const int chunk = z - NCH0;
        if (tid < CPC1) sw[tid] = w1[b * C1 + chunk * CPC1 + tid];
        __syncthreads();

        const int hw = blockIdx.x * 128 + tid;
        if (hw >= HW1) return;
        const float* tp = Tf1 + (size_t)(b * C1 + chunk * CPC1) * HW1 + hw;
        float ac = 0.f, at = 0.f;
        #pragma unroll 8
        for (int c = 0; c < CPC1; ++c) {
            float t = __ldcs(tp + (size_t)c * HW1);
            ac = fmaf(sw[c], t, ac);
            at += t;
        }
        const size_t o = (size_t)(chunk * B + b) * HW1 + hw;
        pc1[o] = ac; pt1[o] = at;
    }
}

// ---------------------------------------------------------------------------
// Phase C1: combine pc chunks -> cam, per-b pre-clamp max + clipped sum.
// 64 blocks x 512 (block = one (level,b)). Last-arriving block computes all
// thresholds, scores and fw.
// ---------------------------------------------------------------------------
__global__ __launch_bounds__(512)
void k_camstat(const float* __restrict__ pc0, const float* __restrict__ pc1,
               float* __restrict__ out) {
    __shared__ float smx[512], ssm[512];
    __shared__ float sscore[64];
    __shared__ int   sflag;
    const int t = threadIdx.x;

    float mx = -CUDART_INF_F, sm = 0.f;
    if (blockIdx.x < 32) {
        const int b = blockIdx.x;
        if (t < HW4_0) {
            float4 cc = {0,0,0,0};
            #pragma unroll
            for (int ch = 0; ch < NCH0; ++ch) {
                const float4 v = reinterpret_cast<const float4*>(pc0)
                                    [(size_t)(ch * B + b) * HW4_0 + t];
                cc.x += v.x; cc.y += v.y; cc.z += v.z; cc.w += v.w;
            }
            d_cam0[b * HW4_0 + t] = cc;
            mx = fmaxf(fmaxf(cc.x, cc.y), fmaxf(cc.z, cc.w));
            sm = fmaxf(cc.x, 0.f) + fmaxf(cc.y, 0.f) + fmaxf(cc.z, 0.f) + fmaxf(cc.w, 0.f);
        }
    } else {
        const int b = blockIdx.x - 32;
        if (t < HW1) {
            float cc = 0.f;
            #pragma unroll
            for (int ch = 0; ch < NCH1; ++ch)
                cc += pc1[(size_t)(ch * B + b) * HW1 + t];
            d_cam1[b * HW1 + t] = cc;
            mx = cc;
            sm = fmaxf(cc, 0.f);
        }
    }

    smx[t] = mx; ssm[t] = sm;
    __syncthreads();
    #pragma unroll
    for (int s = 256; s; s >>= 1) {
        if (t < s) { smx[t] = fmaxf(smx[t], smx[t + s]); ssm[t] += ssm[t + s]; }
        __syncthreads();
    }
    if (t == 0) {
        d_pmax[blockIdx.x] = smx[0];
        d_psum[blockIdx.x] = ssm[0];
        __threadfence();                       // release partials + cam
        const int old = atomicAdd(&d_cnt, 1);
        sflag = (old == 63);
        if (sflag) d_cnt = 0;                  // reset for graph replay
    }
    __syncthreads();
    if (!sflag) return;

    // ---- tail: thresholds, scores, fw (single block, 64 lanes) ----
    if (t < 64) {
        __threadfence();                       // acquire
        const float inv = (t < 32) ? (1.f / HW0) : (1.f / HW1);
        sscore[t] = d_psum[t] * inv;
        d_thr[t]  = fabsf(d_pmax[t] * THRESH);
    }
    __syncthreads();
    if (t == 0) {
        float s0 = 0.f, s1 = 0.f;
        for (int i = 0; i < 32; ++i) { s0 += sscore[i]; s1 += sscore[32 + i]; }
        const float invT = 1.f / (s0 + s1);
        out[OFF_FW + 0] = s0 * invT;
        out[OFF_FW + 1] = s1 * invT;
    }
}

// ---------------------------------------------------------------------------
// Phase C2: mask + write outputs. 92 blocks x 256.
// bids [0,46): level 0 (float4 loads, float2 stores); [46,92): level 1.
// ---------------------------------------------------------------------------
__global__ __launch_bounds__(256)
void k_mask(const float* __restrict__ pt0, const float* __restrict__ ps0,
            const float* __restrict__ pt1, const float* __restrict__ ps1,
            float* __restrict__ out) {
    if (blockIdx.x < 46) {
        const int i = blockIdx.x * 256 + threadIdx.x;   // f4 index, 0..11551
        if (i >= B * HW4_0) return;
        const int b = i / HW4_0, q = i % HW4_0;
        const float thr = d_thr[b];
        const float4 cc = d_cam0[i];

        float4 tt = {0,0,0,0}, ss = {0,0,0,0};
        #pragma unroll
        for (int ch = 0; ch < NCH0; ++ch) {
            const size_t o = (size_t)(ch * B + b) * HW4_0 + q;
            const float4 tv = reinterpret_cast<const float4*>(pt0)[o];
            const float4 sv = reinterpret_cast<const float4*>(ps0)[o];
            tt.x += tv.x; tt.y += tv.y; tt.z += tv.z; tt.w += tv.w;
            ss.x += sv.x; ss.y += sv.y; ss.z += sv.z; ss.w += sv.w;
        }
        constexpr float invC = 1.f / (float)C0;
        float* oT = out + OFF_ET0 + (size_t)b * HW0 + 4 * q;
        float* oS = out + OFF_ES0 + (size_t)b * HW0 + 4 * q;
        // out+2 is 8B-aligned -> float2 stores
        float2 t01 = { cc.x > thr ? tt.x * invC : 0.f, cc.y > thr ? tt.y * invC : 0.f };
        float2 t23 = { cc.z > thr ? tt.z * invC : 0.f, cc.w > thr ? tt.w * invC : 0.f };
        float2 s01 = { cc.x > thr ? ss.x * invC : 0.f, cc.y > thr ? ss.y * invC : 0.f };
        float2 s23 = { cc.z > thr ? ss.z * invC : 0.f, cc.w > thr ? ss.w * invC : 0.f };
        *reinterpret_cast<float2*>(oT)     = t01;
        *reinterpret_cast<float2*>(oT + 2) = t23;
        *reinterpret_cast<float2*>(oS)     = s01;
        *reinterpret_cast<float2*>(oS + 2) = s23;
    } else {
        const int i = (blockIdx.x - 46) * 256 + threadIdx.x;  // px, 0..11551
        if (i >= B * HW1) return;
        const int b = i / HW1, px = i % HW1;
        const float thr = d_thr[32 + b];
        const float cc = d_cam1[i];

        float tt = 0.f, ss = 0.f;
        #pragma unroll
        for (int ch = 0; ch < NCH1; ++ch) {
            const size_t o = (size_t)(ch * B + b) * HW1 + px;
            tt += pt1[o];
            ss += ps1[o];
        }
        constexpr float invC = 1.f / (float)C1;
        const bool m = cc > thr;
        out[OFF_ET1 + i] = m ? tt * invC : 0.f;
        out[OFF_ES1 + i] = m ? ss * invC : 0.f;
    }
}

// ---------------------------------------------------------------------------
extern "C" void kernel_launch(void* const* d_in, const int* in_sizes, int n_in,
                              void* d_out, int out_size) {
    const float* Tf0 = (const float*)d_in[0];
    const float* Tf1 = (const float*)d_in[1];
    const float* Sf0 = (const float*)d_in[2];
    const float* Sf1 = (const float*)d_in[3];
    const float* g0  = (const float*)d_in[4];
    const float* g1  = (const float*)d_in[5];
    float* out = (float*)d_out;

    float *w0, *w1, *pc0, *pt0, *ps0, *pc1, *pt1, *ps1;
    cudaGetSymbolAddress((void**)&w0,  d_w0);
    cudaGetSymbolAddress((void**)&w1,  d_w1);
    cudaGetSymbolAddress((void**)&pc0, d_pc0);
    cudaGetSymbolAddress((void**)&pt0, d_pt0);
    cudaGetSymbolAddress((void**)&ps0, d_ps0);
    cudaGetSymbolAddress((void**)&pc1, d_pc1);
    cudaGetSymbolAddress((void**)&pt1, d_pt1);
    cudaGetSymbolAddress((void**)&ps1, d_ps1);

    // Phase A: gmean + Sf sums, interleaved blocks (284 MB)
    k_phaseA<<<6400, 128>>>(g0, g1, Sf0, Sf1, w0, w1, ps0, ps1);

    // Phase B: Tf pass -> pc, pt (142 MB)
    {
        dim3 grid(3, B, NCH0 + NCH1);   // 2304 blocks of 128
        k_camT<<<grid, 128>>>(Tf0, w0, pc0, pt0, Tf1, w1, pc1, pt1);
    }

    // Phase C1: cam combine + stats + thresholds + fw
    k_camstat<<<64, 512>>>(pc0, pc1, out);

    // Phase C2: mask + outputs
    k_mask<<<92, 256>>>(pt0, ps0, pt1, ps1, out);
}